// round 16
// baseline (speedup 1.0000x reference)
#include <cuda_runtime.h>
#include <cuda_fp16.h>
#include <cstdint>
#include <math.h>
#include <float.h>

#define BATCH 2
#define SEQ   2048
#define DIM   1152
#define NHEAD 16
#define HDIM  72
#define QKPAD 80
#define O3    (3 * DIM)
#define MROWS (BATCH * SEQ)    // 4096
#define BH    (BATCH * NHEAD)  // 32
#define SCALE 0.1178511301977579f
#define QSC   (0.1178511301977579f * 1.4426950408889634f)   // SCALE * log2(e)
#define LN_EPS 1e-5f
#define MFIX  5.0f             // fixed log2-domain offset, folded into QK pad col

// ---------------- scratch ----------------
__device__ __half g_qkv16[(size_t)MROWS * O3];
__device__ __half g_x16[(size_t)MROWS * DIM];
__device__ __half g_wqkv16[(size_t)O3 * DIM];
__device__ __half g_wproj16[(size_t)DIM * DIM];
__device__ __half g_qt[(size_t)BH * SEQ * QKPAD];     // QSC folded; col72 = 1
__device__ __half g_kt[(size_t)BH * SEQ * QKPAD];     // col72 = -MFIX
__device__ __half g_vt[(size_t)BH * SEQ * HDIM];
__device__ __half g_ao[(size_t)MROWS * DIM];

__device__ __forceinline__ uint32_t packh2(float x, float y) {
    __half2 h = __floats2half2_rn(x, y);
    return *(uint32_t*)&h;
}
__device__ __forceinline__ uint32_t s2u(const void* p) {
    return (uint32_t)__cvta_generic_to_shared(p);
}
__device__ __forceinline__ uint32_t ex2h2(float x, float y) {
    uint32_t p = packh2(x, y);
    uint32_t r;
    asm("ex2.approx.f16x2 %0, %1;" : "=r"(r) : "r"(p));
    return r;
}
__device__ __forceinline__ void mma16(float c[4], const uint32_t a[4], const uint32_t b[2]) {
    asm volatile(
        "mma.sync.aligned.m16n8k16.row.col.f32.f16.f16.f32 "
        "{%0,%1,%2,%3}, {%4,%5,%6,%7}, {%8,%9}, {%0,%1,%2,%3};"
        : "+f"(c[0]), "+f"(c[1]), "+f"(c[2]), "+f"(c[3])
        : "r"(a[0]), "r"(a[1]), "r"(a[2]), "r"(a[3]), "r"(b[0]), "r"(b[1]));
}
__device__ __forceinline__ void ldm4(uint32_t r[4], uint32_t a) {
    asm volatile("ldmatrix.sync.aligned.m8n8.x4.shared.b16 {%0,%1,%2,%3}, [%4];"
        : "=r"(r[0]), "=r"(r[1]), "=r"(r[2]), "=r"(r[3]) : "r"(a));
}
__device__ __forceinline__ void ldm4t(uint32_t r[4], uint32_t a) {
    asm volatile("ldmatrix.sync.aligned.m8n8.x4.trans.shared.b16 {%0,%1,%2,%3}, [%4];"
        : "=r"(r[0]), "=r"(r[1]), "=r"(r[2]), "=r"(r[3]) : "r"(a));
}
__device__ __forceinline__ void cp16(uint32_t dst, const void* src) {
    asm volatile("cp.async.ca.shared.global [%0], [%1], 16;" :: "r"(dst), "l"(src));
}
#define CP_COMMIT() asm volatile("cp.async.commit_group;" ::: "memory")
#define CP_WAIT1()  asm volatile("cp.async.wait_group 1;" ::: "memory")

// ---------------- fused fp32 -> fp16 convert ----------------
__global__ void f2h3(const float* __restrict__ s0, __half* __restrict__ d0, int n0,
                     const float* __restrict__ s1, __half* __restrict__ d1, int n1,
                     const float* __restrict__ s2, __half* __restrict__ d2, int n2)
{
    int i = blockIdx.x * blockDim.x + threadIdx.x;
    const float* s; __half* d; int j;
    if (i < n0)                { s = s0; d = d0; j = i; }
    else if (i < n0 + n1)      { s = s1; d = d1; j = i - n0; }
    else if (i < n0 + n1 + n2) { s = s2; d = d2; j = i - n0 - n1; }
    else return;
    float4 v = ((const float4*)s)[j];
    ((uint2*)d)[j] = make_uint2(packh2(v.x, v.y), packh2(v.z, v.w));
}

// ================= fp16 GEMM v5: 128x128 block, 128 thr, K-chunk 64, 3-stage =====
template<bool C16>
__global__ __launch_bounds__(128)
void hgemm(const __half* __restrict__ A, const __half* __restrict__ B,
           const float* __restrict__ bias, void* __restrict__ C_,
           int K, int lda, int ldb, int ldc)
{
    extern __shared__ __half smh[];
    constexpr int PAD = 72;              // 64 data + 8 pad halves; 144 B pitch
    constexpr int STG = 256 * PAD;       // A(128 rows) + B(128 rows) per stage
    constexpr int BOF = 128 * PAD;

    const int tid = threadIdx.x, wid = tid >> 5, lane = tid & 31;
    const int g = lane >> 2, t = lane & 3;
    const int l8 = lane & 7, mi = lane >> 3;
    const int mrow = (mi & 1) * 8 + l8;
    const int mkof = (mi >> 1) * 8;
    const int wm = wid >> 1, wn = wid & 1;
    const int m0 = blockIdx.y * 128, n0 = blockIdx.x * 128;
    const int ar = tid >> 3, ac = (tid & 7) * 8;   // 16 rows per pass, 8 groups/row

    const uint32_t sb = s2u(smh);
    float*  Cf = (float*)C_;
    __half* Ch = (__half*)C_;

    float acc[4][8][4];
#pragma unroll
    for (int mt = 0; mt < 4; mt++)
#pragma unroll
        for (int nt = 0; nt < 8; nt++)
#pragma unroll
            for (int j = 0; j < 4; j++) acc[mt][nt][j] = 0.f;

    auto load_chunk = [&](int c) {
        const int k0 = c * 64;
        const uint32_t da = sb + ((c % 3) * STG) * 2;
        const uint32_t db = da + BOF * 2;
#pragma unroll
        for (int i = 0; i < 8; i++) {
            cp16(da + ((ar + i * 16) * PAD + ac) * 2,
                 A + (size_t)(m0 + ar + i * 16) * lda + k0 + ac);
            cp16(db + ((ar + i * 16) * PAD + ac) * 2,
                 B + (size_t)(n0 + ar + i * 16) * ldb + k0 + ac);
        }
    };

    const int nch = K / 64;
    load_chunk(0); CP_COMMIT();
    load_chunk(1); CP_COMMIT();

    for (int c = 0; c < nch; c++) {
        CP_WAIT1();
        __syncthreads();
        if (c + 2 < nch) load_chunk(c + 2);
        CP_COMMIT();

        const uint32_t ab = sb + ((c % 3) * STG) * 2;
        const uint32_t bb = ab + BOF * 2;
#pragma unroll
        for (int ks = 0; ks < 4; ks++) {
            const int kk = ks * 16;
            uint32_t af[4][4], bf[4][4];
#pragma unroll
            for (int mt = 0; mt < 4; mt++)
                ldm4(af[mt], ab + ((wm * 64 + mt * 16 + mrow) * PAD + kk + mkof) * 2);
#pragma unroll
            for (int np = 0; np < 4; np++)
                ldm4(bf[np], bb + ((wn * 64 + np * 16 + mrow) * PAD + kk + mkof) * 2);
#pragma unroll
            for (int mt = 0; mt < 4; mt++)
#pragma unroll
                for (int np = 0; np < 4; np++) {
                    uint32_t b0[2] = { bf[np][0], bf[np][2] };
                    uint32_t b1[2] = { bf[np][1], bf[np][3] };
                    mma16(acc[mt][2 * np],     af[mt], b0);
                    mma16(acc[mt][2 * np + 1], af[mt], b1);
                }
        }
    }

#pragma unroll
    for (int mt = 0; mt < 4; mt++) {
        const int r0 = m0 + wm * 64 + mt * 16 + g;
#pragma unroll
        for (int nt = 0; nt < 8; nt++) {
            const int col = n0 + wn * 64 + nt * 8 + 2 * t;
            const float bx = bias[col], by = bias[col + 1];
            const float v0 = acc[mt][nt][0] + bx, v1 = acc[mt][nt][1] + by;
            const float v2 = acc[mt][nt][2] + bx, v3 = acc[mt][nt][3] + by;
            if (C16) {
                *(__half2*)(Ch + (size_t)r0 * ldc + col)       = __floats2half2_rn(v0, v1);
                *(__half2*)(Ch + (size_t)(r0 + 8) * ldc + col) = __floats2half2_rn(v2, v3);
            } else {
                *(float2*)(Cf + (size_t)r0 * ldc + col)        = make_float2(v0, v1);
                *(float2*)(Cf + (size_t)(r0 + 8) * ldc + col)  = make_float2(v2, v3);
            }
        }
    }
}

// ------------- LayerNorm(q,k) + QSC + transpose (fp16 in) -> fp16 ----
__global__ __launch_bounds__(256)
void ln_split(const __half* __restrict__ qkv,
              const float* __restrict__ qg, const float* __restrict__ qb,
              const float* __restrict__ kg, const float* __restrict__ kb,
              __half* __restrict__ qt, __half* __restrict__ kt, __half* __restrict__ vt)
{
    int task = blockIdx.x * 8 + (threadIdx.x >> 5);
    if (task >= BATCH * SEQ * NHEAD) return;
    const int lane = threadIdx.x & 31;
    const int h = task % NHEAD;
    const int n = (task / NHEAD) % SEQ;
    const int b = task / (NHEAD * SEQ);
    const int bh = b * NHEAD + h;

    const size_t ibase = ((size_t)(b * SEQ + n) * 3) * DIM + h * HDIM;
    const size_t oqk = ((size_t)bh * SEQ + n) * QKPAD;

    const __half* q = qkv + ibase;
    const __half* k = qkv + ibase + DIM;
    const __half* v = qkv + ibase + 2 * DIM;

    {
        float x0 = __half2float(q[lane]), x1 = __half2float(q[lane + 32]);
        float x2 = (lane < 8) ? __half2float(q[lane + 64]) : 0.f;
        float s = x0 + x1 + x2;
#pragma unroll
        for (int o = 16; o; o >>= 1) s += __shfl_xor_sync(0xffffffffu, s, o);
        const float mu = s * (1.0f / HDIM);
        float d0 = x0 - mu, d1 = x1 - mu, d2 = (lane < 8) ? (x2 - mu) : 0.f;
        float vs = d0 * d0 + d1 * d1 + d2 * d2;
#pragma unroll
        for (int o = 16; o; o >>= 1) vs += __shfl_xor_sync(0xffffffffu, vs, o);
        const float inv = rsqrtf(vs * (1.0f / HDIM) + LN_EPS);
        qt[oqk + lane]      = __float2half_rn((d0 * inv * qg[lane]      + qb[lane])      * QSC);
        qt[oqk + lane + 32] = __float2half_rn((d1 * inv * qg[lane + 32] + qb[lane + 32]) * QSC);
        if (lane < 16) {
            float pv;
            if (lane < 8)       pv = (d2 * inv * qg[lane + 64] + qb[lane + 64]) * QSC;
            else if (lane == 8) pv = 1.0f;             // col 72: offset carrier
            else                pv = 0.f;
            qt[oqk + lane + 64] = __float2half_rn(pv);
        }
    }
    {
        float x0 = __half2float(k[lane]), x1 = __half2float(k[lane + 32]);
        float x2 = (lane < 8) ? __half2float(k[lane + 64]) : 0.f;
        float s = x0 + x1 + x2;
#pragma unroll
        for (int o = 16; o; o >>= 1) s += __shfl_xor_sync(0xffffffffu, s, o);
        const float mu = s * (1.0f / HDIM);
        float d0 = x0 - mu, d1 = x1 - mu, d2 = (lane < 8) ? (x2 - mu) : 0.f;
        float vs = d0 * d0 + d1 * d1 + d2 * d2;
#pragma unroll
        for (int o = 16; o; o >>= 1) vs += __shfl_xor_sync(0xffffffffu, vs, o);
        const float inv = rsqrtf(vs * (1.0f / HDIM) + LN_EPS);
        kt[oqk + lane]      = __float2half_rn(d0 * inv * kg[lane]      + kb[lane]);
        kt[oqk + lane + 32] = __float2half_rn(d1 * inv * kg[lane + 32] + kb[lane + 32]);
        if (lane < 16) {
            float pv;
            if (lane < 8)       pv = d2 * inv * kg[lane + 64] + kb[lane + 64];
            else if (lane == 8) pv = -MFIX;            // col 72: -offset
            else                pv = 0.f;
            kt[oqk + lane + 64] = __float2half_rn(pv);
        }
    }
    {
        __half* vb = vt + ((size_t)bh * SEQ + n) * HDIM;
        vb[lane]      = v[lane];
        vb[lane + 32] = v[lane + 32];
        if (lane < 8) vb[lane + 64] = v[lane + 64];
    }
}

// ================= fused flash attention v10b: folded fixed-offset softmax =========
#define TK 64
#define NTI (SEQ / TK)          // 32
#define QSTR 88
#define VSTR 88                 // col 72 = 1.0, 73..79 = 0
#define SMH_Q 0
#define SMH_K (128 * QSTR)
#define SMH_V (SMH_K + 3 * TK * QSTR)
#define SM_FLASH ((SMH_V + 3 * TK * VSTR) * 2)    // 90112 B

__global__ __launch_bounds__(256, 2)
void flash_attn(const __half* __restrict__ qt, const __half* __restrict__ kt,
                const __half* __restrict__ vt, __half* __restrict__ ao)
{
    extern __shared__ __half smh[];
    const int tid = threadIdx.x, wid = tid >> 5, lane = tid & 31;
    const int g = lane >> 2, t = lane & 3;
    const int l8 = lane & 7, mi = lane >> 3;
    const int mrow = (mi & 1) * 8 + l8;
    const int mkof = (mi >> 1) * 8;
    const int m0 = blockIdx.x * 128;
    const int bh = blockIdx.y;

    const __half* Qg = qt + ((size_t)bh * SEQ + m0) * QKPAD;
    const __half* Kg = kt + (size_t)bh * SEQ * QKPAD;
    const __half* Vg = vt + (size_t)bh * SEQ * HDIM;

    const uint32_t sb = s2u(smh);

    for (int idx = tid; idx < 1280; idx += 256) {
        int r = idx / 10, c8 = (idx % 10) * 8;
        *(uint4*)(smh + SMH_Q + r * QSTR + c8) = *(const uint4*)(Qg + (size_t)r * QKPAD + c8);
    }
    if (tid < 3 * TK) {   // V cols 72..79: {1,0,0,0,0,0,0,0}
        uint4 ones = make_uint4(0x00003C00u, 0u, 0u, 0u);
        *(uint4*)(smh + SMH_V + tid * VSTR + 72) = ones;
    }

    auto load_kv = [&](int ti) {
        const int buf = ti % 3;
        const int n0 = ti * TK;
        const uint32_t kd = sb + (SMH_K + buf * TK * QSTR) * 2;
#pragma unroll
        for (int i = 0; i < 3; i++) {
            int idx = tid + i * 256;
            if (idx < 640) {
                int r = idx / 10, c8 = (idx % 10) * 8;
                cp16(kd + (r * QSTR + c8) * 2, Kg + (size_t)(n0 + r) * QKPAD + c8);
            }
        }
        const uint32_t vd = sb + (SMH_V + buf * TK * VSTR) * 2;
#pragma unroll
        for (int i = 0; i < 3; i++) {
            int idx = tid + i * 256;
            if (idx < 576) {
                int r = idx / 9, c8 = (idx % 9) * 8;
                cp16(vd + (r * VSTR + c8) * 2, Vg + (size_t)(n0 + r) * HDIM + c8);
            }
        }
    };

    load_kv(0); CP_COMMIT();
    load_kv(1); CP_COMMIT();

    float oacc[10][4];
#pragma unroll
    for (int nt = 0; nt < 10; nt++)
#pragma unroll
        for (int j = 0; j < 4; j++) oacc[nt][j] = 0.f;

    uint32_t qf[5][4];
    bool qloaded = false;

    for (int ti = 0; ti < NTI; ti++) {
        CP_WAIT1();
        __syncthreads();
        if (ti + 2 < NTI) load_kv(ti + 2);
        CP_COMMIT();

        if (!qloaded) {
            qloaded = true;
#pragma unroll
            for (int s = 0; s < 5; s++)
                ldm4(qf[s], sb + (SMH_Q + (wid * 16 + mrow) * QSTR + s * 16 + mkof) * 2);
        }
        const uint32_t kbase = sb + (SMH_K + (ti % 3) * TK * QSTR) * 2;
        const uint32_t vbase = sb + (SMH_V + (ti % 3) * TK * VSTR) * 2;

        // ---- S = Q @ K^T - MFIX (offset in pad col) ----
        float sacc[8][4];
#pragma unroll
        for (int nt = 0; nt < 8; nt++)
#pragma unroll
            for (int j = 0; j < 4; j++) sacc[nt][j] = 0.f;
#pragma unroll
        for (int s = 0; s < 5; s++) {
#pragma unroll
            for (int np = 0; np < 4; np++) {
                uint32_t kf[4];
                ldm4(kf, kbase + ((np * 16 + mrow) * QSTR + s * 16 + mkof) * 2);
                uint32_t b0[2] = { kf[0], kf[2] }, b1[2] = { kf[1], kf[3] };
                mma16(sacc[2 * np],     qf[s], b0);
                mma16(sacc[2 * np + 1], qf[s], b1);
            }
        }

        // ---- P = 2^sacc packed fp16x2; O += P @ V ----
#pragma unroll
        for (int j = 0; j < 4; j++) {
            uint32_t a[4] = {
                ex2h2(sacc[2 * j][0],     sacc[2 * j][1]),
                ex2h2(sacc[2 * j][2],     sacc[2 * j][3]),
                ex2h2(sacc[2 * j + 1][0], sacc[2 * j + 1][1]),
                ex2h2(sacc[2 * j + 1][2], sacc[2 * j + 1][3]) };
            const uint32_t vrow = vbase + ((j * 16 + mrow) * VSTR) * 2;
#pragma unroll
            for (int np = 0; np < 5; np++) {   // np=4 covers cols 64..79 (incl. ones col)
                uint32_t vf[4];
                ldm4t(vf, vrow + np * 32 + (mi >> 1) * 16);
                uint32_t b0[2] = { vf[0], vf[1] }, b1[2] = { vf[2], vf[3] };
                mma16(oacc[2 * np],     a, b0);
                mma16(oacc[2 * np + 1], a, b1);
            }
        }
    }

    // ---- epilogue: l from ones column (oacc[9]) ----
    const float l_lo = __shfl_sync(0xffffffffu, oacc[9][0], lane & 28);
    const float l_hi = __shfl_sync(0xffffffffu, oacc[9][2], lane & 28);
    const float inv_lo = 1.f / l_lo, inv_hi = 1.f / l_hi;
    const int b = bh >> 4, h = bh & 15;
    const int n_lo = m0 + wid * 16 + g;
    __half* po_lo = ao + ((size_t)(b * SEQ) + n_lo) * DIM + h * HDIM;
    __half* po_hi = po_lo + (size_t)8 * DIM;
#pragma unroll
    for (int nt = 0; nt < 9; nt++) {
        const int col = nt * 8 + 2 * t;
        *(__half2*)(po_lo + col) = __floats2half2_rn(oacc[nt][0] * inv_lo, oacc[nt][1] * inv_lo);
        *(__half2*)(po_hi + col) = __floats2half2_rn(oacc[nt][2] * inv_hi, oacc[nt][3] * inv_hi);
    }
}

// ---------------- host launcher ----------------
extern "C" void kernel_launch(void* const* d_in, const int* in_sizes, int n_in,
                              void* d_out, int out_size)
{
    const float* x      = (const float*)d_in[0];
    const float* w_qkv  = (const float*)d_in[1];
    const float* b_qkv  = (const float*)d_in[2];
    const float* q_g    = (const float*)d_in[3];
    const float* q_b    = (const float*)d_in[4];
    const float* k_g    = (const float*)d_in[5];
    const float* k_b    = (const float*)d_in[6];
    const float* w_proj = (const float*)d_in[7];
    const float* b_proj = (const float*)d_in[8];
    float* out = (float*)d_out;

    void *p_qkv16, *p_x16, *p_wqkv16, *p_wproj16, *p_qt, *p_kt, *p_vt, *p_ao;
    cudaGetSymbolAddress(&p_qkv16,   g_qkv16);
    cudaGetSymbolAddress(&p_x16,     g_x16);
    cudaGetSymbolAddress(&p_wqkv16,  g_wqkv16);
    cudaGetSymbolAddress(&p_wproj16, g_wproj16);
    cudaGetSymbolAddress(&p_qt,      g_qt);
    cudaGetSymbolAddress(&p_kt,      g_kt);
    cudaGetSymbolAddress(&p_vt,      g_vt);
    cudaGetSymbolAddress(&p_ao,      g_ao);

    const int smemG = 3 * 256 * 72 * 2;   // 110592 B per CTA (3-stage, chunk 64)
    cudaFuncSetAttribute(hgemm<true>,  cudaFuncAttributeMaxDynamicSharedMemorySize, smemG);
    cudaFuncSetAttribute(hgemm<false>, cudaFuncAttributeMaxDynamicSharedMemorySize, smemG);
    cudaFuncSetAttribute(flash_attn, cudaFuncAttributeMaxDynamicSharedMemorySize, SM_FLASH);

    // 0) fp32 -> fp16 conversion
    const int n0 = MROWS * DIM / 4, n1 = O3 * DIM / 4, n2 = DIM * DIM / 4;
    f2h3<<<(n0 + n1 + n2 + 255) / 256, 256>>>(
        x, (__half*)p_x16, n0,
        w_qkv, (__half*)p_wqkv16, n1,
        w_proj, (__half*)p_wproj16, n2);

    // 1) QKV GEMM -> fp16
    hgemm<true><<<dim3(O3 / 128, MROWS / 128), 128, smemG>>>(
        (const __half*)p_x16, (const __half*)p_wqkv16, b_qkv, p_qkv16,
        DIM, DIM, DIM, O3);

    // 2) LayerNorm + transpose -> fp16 (offset carriers in pad col)
    ln_split<<<(BATCH * SEQ * NHEAD) / 8, 256>>>(
        (const __half*)p_qkv16, q_g, q_b, k_g, k_b,
        (__half*)p_qt, (__half*)p_kt, (__half*)p_vt);

    // 3) fused attention
    flash_attn<<<dim3(SEQ / 128, BH), 256, SM_FLASH>>>(
        (const __half*)p_qt, (const __half*)p_kt, (const __half*)p_vt, (__half*)p_ao);

    // 4) projection -> fp32 out
    hgemm<false><<<dim3(DIM / 128, MROWS / 128), 128, smemG>>>(
        (const __half*)p_ao, (const __half*)p_wproj16, b_proj, out,
        DIM, DIM, DIM, DIM);
}

// round 17
// speedup vs baseline: 1.0249x; 1.0249x over previous
#include <cuda_runtime.h>
#include <cuda_fp16.h>
#include <cstdint>
#include <math.h>
#include <float.h>

#define BATCH 2
#define SEQ   2048
#define DIM   1152
#define NHEAD 16
#define HDIM  72
#define QKPAD 80
#define O3    (3 * DIM)
#define MROWS (BATCH * SEQ)    // 4096
#define BH    (BATCH * NHEAD)  // 32
#define SCALE 0.1178511301977579f
#define QSC   (0.1178511301977579f * 1.4426950408889634f)   // SCALE * log2(e)
#define LN_EPS 1e-5f
#define MFIX  5.0f             // fixed log2-domain offset, folded into QK pad col

// ---------------- scratch ----------------
__device__ __half g_qkv16[(size_t)MROWS * O3];
__device__ __half g_x16[(size_t)MROWS * DIM];
__device__ __half g_wqkv16[(size_t)O3 * DIM];
__device__ __half g_wproj16[(size_t)DIM * DIM];
__device__ __half g_qt[(size_t)BH * SEQ * QKPAD];     // QSC folded; col72 = 1
__device__ __half g_kt[(size_t)BH * SEQ * QKPAD];     // col72 = -MFIX
__device__ __half g_vt[(size_t)BH * SEQ * HDIM];
__device__ __half g_ao[(size_t)MROWS * DIM];

__device__ __forceinline__ uint32_t packh2(float x, float y) {
    __half2 h = __floats2half2_rn(x, y);
    return *(uint32_t*)&h;
}
__device__ __forceinline__ uint32_t s2u(const void* p) {
    return (uint32_t)__cvta_generic_to_shared(p);
}
__device__ __forceinline__ uint32_t ex2h2(float x, float y) {
    uint32_t p = packh2(x, y);
    uint32_t r;
    asm("ex2.approx.f16x2 %0, %1;" : "=r"(r) : "r"(p));
    return r;
}
__device__ __forceinline__ void mma16(float c[4], const uint32_t a[4], const uint32_t b[2]) {
    asm volatile(
        "mma.sync.aligned.m16n8k16.row.col.f32.f16.f16.f32 "
        "{%0,%1,%2,%3}, {%4,%5,%6,%7}, {%8,%9}, {%0,%1,%2,%3};"
        : "+f"(c[0]), "+f"(c[1]), "+f"(c[2]), "+f"(c[3])
        : "r"(a[0]), "r"(a[1]), "r"(a[2]), "r"(a[3]), "r"(b[0]), "r"(b[1]));
}
__device__ __forceinline__ void ldm4(uint32_t r[4], uint32_t a) {
    asm volatile("ldmatrix.sync.aligned.m8n8.x4.shared.b16 {%0,%1,%2,%3}, [%4];"
        : "=r"(r[0]), "=r"(r[1]), "=r"(r[2]), "=r"(r[3]) : "r"(a));
}
__device__ __forceinline__ void ldm4t(uint32_t r[4], uint32_t a) {
    asm volatile("ldmatrix.sync.aligned.m8n8.x4.trans.shared.b16 {%0,%1,%2,%3}, [%4];"
        : "=r"(r[0]), "=r"(r[1]), "=r"(r[2]), "=r"(r[3]) : "r"(a));
}
__device__ __forceinline__ void cp16(uint32_t dst, const void* src) {
    asm volatile("cp.async.ca.shared.global [%0], [%1], 16;" :: "r"(dst), "l"(src));
}
#define CP_COMMIT() asm volatile("cp.async.commit_group;" ::: "memory")
#define CP_WAIT1()  asm volatile("cp.async.wait_group 1;" ::: "memory")
#define CP_WAIT2()  asm volatile("cp.async.wait_group 2;" ::: "memory")

// ---------------- fused fp32 -> fp16 convert ----------------
__global__ void f2h3(const float* __restrict__ s0, __half* __restrict__ d0, int n0,
                     const float* __restrict__ s1, __half* __restrict__ d1, int n1,
                     const float* __restrict__ s2, __half* __restrict__ d2, int n2)
{
    int i = blockIdx.x * blockDim.x + threadIdx.x;
    const float* s; __half* d; int j;
    if (i < n0)                { s = s0; d = d0; j = i; }
    else if (i < n0 + n1)      { s = s1; d = d1; j = i - n0; }
    else if (i < n0 + n1 + n2) { s = s2; d = d2; j = i - n0 - n1; }
    else return;
    float4 v = ((const float4*)s)[j];
    ((uint2*)d)[j] = make_uint2(packh2(v.x, v.y), packh2(v.z, v.w));
}

// ================= fp16 GEMM (R15): 128x128 block, 128 thr, 4-stage chunk-32 =====
template<bool C16>
__global__ __launch_bounds__(128)
void hgemm(const __half* __restrict__ A, const __half* __restrict__ B,
           const float* __restrict__ bias, void* __restrict__ C_,
           int K, int lda, int ldb, int ldc)
{
    extern __shared__ __half smh[];
    constexpr int PAD = 40;
    constexpr int STG = 256 * PAD;
    constexpr int BOF = 128 * PAD;

    const int tid = threadIdx.x, wid = tid >> 5, lane = tid & 31;
    const int g = lane >> 2, t = lane & 3;
    const int l8 = lane & 7, mi = lane >> 3;
    const int mrow = (mi & 1) * 8 + l8;
    const int mkof = (mi >> 1) * 8;
    const int wm = wid >> 1, wn = wid & 1;
    const int m0 = blockIdx.y * 128, n0 = blockIdx.x * 128;
    const int ar = tid >> 2, ac = (tid & 3) * 8;

    const uint32_t sb = s2u(smh);
    float*  Cf = (float*)C_;
    __half* Ch = (__half*)C_;

    float acc[4][8][4];
#pragma unroll
    for (int mt = 0; mt < 4; mt++)
#pragma unroll
        for (int nt = 0; nt < 8; nt++)
#pragma unroll
            for (int j = 0; j < 4; j++) acc[mt][nt][j] = 0.f;

    auto load_chunk = [&](int c) {
        const int k0 = c * 32;
        const uint32_t da = sb + ((c & 3) * STG) * 2;
        const uint32_t db = da + BOF * 2;
#pragma unroll
        for (int i = 0; i < 4; i++) {
            cp16(da + ((ar + i * 32) * PAD + ac) * 2,
                 A + (size_t)(m0 + ar + i * 32) * lda + k0 + ac);
            cp16(db + ((ar + i * 32) * PAD + ac) * 2,
                 B + (size_t)(n0 + ar + i * 32) * ldb + k0 + ac);
        }
    };

    const int nch = K / 32;
    load_chunk(0); CP_COMMIT();
    load_chunk(1); CP_COMMIT();
    load_chunk(2); CP_COMMIT();

    for (int c = 0; c < nch; c++) {
        CP_WAIT2();
        __syncthreads();
        if (c + 3 < nch) load_chunk(c + 3);
        CP_COMMIT();

        const uint32_t ab = sb + ((c & 3) * STG) * 2;
        const uint32_t bb = ab + BOF * 2;
#pragma unroll
        for (int ks = 0; ks < 2; ks++) {
            const int kk = ks * 16;
            uint32_t af[4][4], bf[4][4];
#pragma unroll
            for (int mt = 0; mt < 4; mt++)
                ldm4(af[mt], ab + ((wm * 64 + mt * 16 + mrow) * PAD + kk + mkof) * 2);
#pragma unroll
            for (int np = 0; np < 4; np++)
                ldm4(bf[np], bb + ((wn * 64 + np * 16 + mrow) * PAD + kk + mkof) * 2);
#pragma unroll
            for (int mt = 0; mt < 4; mt++)
#pragma unroll
                for (int np = 0; np < 4; np++) {
                    uint32_t b0[2] = { bf[np][0], bf[np][2] };
                    uint32_t b1[2] = { bf[np][1], bf[np][3] };
                    mma16(acc[mt][2 * np],     af[mt], b0);
                    mma16(acc[mt][2 * np + 1], af[mt], b1);
                }
        }
    }

#pragma unroll
    for (int mt = 0; mt < 4; mt++) {
        const int r0 = m0 + wm * 64 + mt * 16 + g;
#pragma unroll
        for (int nt = 0; nt < 8; nt++) {
            const int col = n0 + wn * 64 + nt * 8 + 2 * t;
            const float bx = bias[col], by = bias[col + 1];
            const float v0 = acc[mt][nt][0] + bx, v1 = acc[mt][nt][1] + by;
            const float v2 = acc[mt][nt][2] + bx, v3 = acc[mt][nt][3] + by;
            if (C16) {
                *(__half2*)(Ch + (size_t)r0 * ldc + col)       = __floats2half2_rn(v0, v1);
                *(__half2*)(Ch + (size_t)(r0 + 8) * ldc + col) = __floats2half2_rn(v2, v3);
            } else {
                *(float2*)(Cf + (size_t)r0 * ldc + col)        = make_float2(v0, v1);
                *(float2*)(Cf + (size_t)(r0 + 8) * ldc + col)  = make_float2(v2, v3);
            }
        }
    }
}

// ------------- LayerNorm(q,k) + QSC + transpose (fp16 in) -> fp16 ----
// qt pad col72 = 1.0, kt pad col72 = -MFIX: QK mma computes s - MFIX directly.
__global__ __launch_bounds__(256)
void ln_split(const __half* __restrict__ qkv,
              const float* __restrict__ qg, const float* __restrict__ qb,
              const float* __restrict__ kg, const float* __restrict__ kb,
              __half* __restrict__ qt, __half* __restrict__ kt, __half* __restrict__ vt)
{
    int task = blockIdx.x * 8 + (threadIdx.x >> 5);
    if (task >= BATCH * SEQ * NHEAD) return;
    const int lane = threadIdx.x & 31;
    const int h = task % NHEAD;
    const int n = (task / NHEAD) % SEQ;
    const int b = task / (NHEAD * SEQ);
    const int bh = b * NHEAD + h;

    const size_t ibase = ((size_t)(b * SEQ + n) * 3) * DIM + h * HDIM;
    const size_t oqk = ((size_t)bh * SEQ + n) * QKPAD;

    const __half* q = qkv + ibase;
    const __half* k = qkv + ibase + DIM;
    const __half* v = qkv + ibase + 2 * DIM;

    {
        float x0 = __half2float(q[lane]), x1 = __half2float(q[lane + 32]);
        float x2 = (lane < 8) ? __half2float(q[lane + 64]) : 0.f;
        float s = x0 + x1 + x2;
#pragma unroll
        for (int o = 16; o; o >>= 1) s += __shfl_xor_sync(0xffffffffu, s, o);
        const float mu = s * (1.0f / HDIM);
        float d0 = x0 - mu, d1 = x1 - mu, d2 = (lane < 8) ? (x2 - mu) : 0.f;
        float vs = d0 * d0 + d1 * d1 + d2 * d2;
#pragma unroll
        for (int o = 16; o; o >>= 1) vs += __shfl_xor_sync(0xffffffffu, vs, o);
        const float inv = rsqrtf(vs * (1.0f / HDIM) + LN_EPS);
        qt[oqk + lane]      = __float2half_rn((d0 * inv * qg[lane]      + qb[lane])      * QSC);
        qt[oqk + lane + 32] = __float2half_rn((d1 * inv * qg[lane + 32] + qb[lane + 32]) * QSC);
        if (lane < 16) {
            float pv;
            if (lane < 8)       pv = (d2 * inv * qg[lane + 64] + qb[lane + 64]) * QSC;
            else if (lane == 8) pv = 1.0f;             // col 72: offset carrier
            else                pv = 0.f;
            qt[oqk + lane + 64] = __float2half_rn(pv);
        }
    }
    {
        float x0 = __half2float(k[lane]), x1 = __half2float(k[lane + 32]);
        float x2 = (lane < 8) ? __half2float(k[lane + 64]) : 0.f;
        float s = x0 + x1 + x2;
#pragma unroll
        for (int o = 16; o; o >>= 1) s += __shfl_xor_sync(0xffffffffu, s, o);
        const float mu = s * (1.0f / HDIM);
        float d0 = x0 - mu, d1 = x1 - mu, d2 = (lane < 8) ? (x2 - mu) : 0.f;
        float vs = d0 * d0 + d1 * d1 + d2 * d2;
#pragma unroll
        for (int o = 16; o; o >>= 1) vs += __shfl_xor_sync(0xffffffffu, vs, o);
        const float inv = rsqrtf(vs * (1.0f / HDIM) + LN_EPS);
        kt[oqk + lane]      = __float2half_rn(d0 * inv * kg[lane]      + kb[lane]);
        kt[oqk + lane + 32] = __float2half_rn(d1 * inv * kg[lane + 32] + kb[lane + 32]);
        if (lane < 16) {
            float pv;
            if (lane < 8)       pv = d2 * inv * kg[lane + 64] + kb[lane + 64];
            else if (lane == 8) pv = -MFIX;            // col 72: -offset
            else                pv = 0.f;
            kt[oqk + lane + 64] = __float2half_rn(pv);
        }
    }
    {
        __half* vb = vt + ((size_t)bh * SEQ + n) * HDIM;
        vb[lane]      = v[lane];
        vb[lane + 32] = v[lane + 32];
        if (lane < 8) vb[lane + 64] = v[lane + 64];
    }
}

// ================= fused flash attention v10b: folded fixed-offset softmax =========
#define TK 64
#define NTI (SEQ / TK)          // 32
#define QSTR 88
#define VSTR 88                 // col 72 = 1.0, 73..79 = 0
#define SMH_Q 0
#define SMH_K (128 * QSTR)
#define SMH_V (SMH_K + 3 * TK * QSTR)
#define SM_FLASH ((SMH_V + 3 * TK * VSTR) * 2)    // 90112 B

__global__ __launch_bounds__(256, 2)
void flash_attn(const __half* __restrict__ qt, const __half* __restrict__ kt,
                const __half* __restrict__ vt, __half* __restrict__ ao)
{
    extern __shared__ __half smh[];
    const int tid = threadIdx.x, wid = tid >> 5, lane = tid & 31;
    const int g = lane >> 2, t = lane & 3;
    const int l8 = lane & 7, mi = lane >> 3;
    const int mrow = (mi & 1) * 8 + l8;
    const int mkof = (mi >> 1) * 8;
    const int m0 = blockIdx.x * 128;
    const int bh = blockIdx.y;

    const __half* Qg = qt + ((size_t)bh * SEQ + m0) * QKPAD;
    const __half* Kg = kt + (size_t)bh * SEQ * QKPAD;
    const __half* Vg = vt + (size_t)bh * SEQ * HDIM;

    const uint32_t sb = s2u(smh);

    for (int idx = tid; idx < 1280; idx += 256) {
        int r = idx / 10, c8 = (idx % 10) * 8;
        *(uint4*)(smh + SMH_Q + r * QSTR + c8) = *(const uint4*)(Qg + (size_t)r * QKPAD + c8);
    }
    if (tid < 3 * TK) {   // V cols 72..79: {1,0,0,0,0,0,0,0}
        uint4 ones = make_uint4(0x00003C00u, 0u, 0u, 0u);
        *(uint4*)(smh + SMH_V + tid * VSTR + 72) = ones;
    }

    auto load_kv = [&](int ti) {
        const int buf = ti % 3;
        const int n0 = ti * TK;
        const uint32_t kd = sb + (SMH_K + buf * TK * QSTR) * 2;
#pragma unroll
        for (int i = 0; i < 3; i++) {
            int idx = tid + i * 256;
            if (idx < 640) {
                int r = idx / 10, c8 = (idx % 10) * 8;
                cp16(kd + (r * QSTR + c8) * 2, Kg + (size_t)(n0 + r) * QKPAD + c8);
            }
        }
        const uint32_t vd = sb + (SMH_V + buf * TK * VSTR) * 2;
#pragma unroll
        for (int i = 0; i < 3; i++) {
            int idx = tid + i * 256;
            if (idx < 576) {
                int r = idx / 9, c8 = (idx % 9) * 8;
                cp16(vd + (r * VSTR + c8) * 2, Vg + (size_t)(n0 + r) * HDIM + c8);
            }
        }
    };

    load_kv(0); CP_COMMIT();
    load_kv(1); CP_COMMIT();

    float oacc[10][4];
#pragma unroll
    for (int nt = 0; nt < 10; nt++)
#pragma unroll
        for (int j = 0; j < 4; j++) oacc[nt][j] = 0.f;

    uint32_t qf[5][4];
    bool qloaded = false;

    for (int ti = 0; ti < NTI; ti++) {
        CP_WAIT1();
        __syncthreads();
        if (ti + 2 < NTI) load_kv(ti + 2);
        CP_COMMIT();

        if (!qloaded) {
            qloaded = true;
#pragma unroll
            for (int s = 0; s < 5; s++)
                ldm4(qf[s], sb + (SMH_Q + (wid * 16 + mrow) * QSTR + s * 16 + mkof) * 2);
        }
        const uint32_t kbase = sb + (SMH_K + (ti % 3) * TK * QSTR) * 2;
        const uint32_t vbase = sb + (SMH_V + (ti % 3) * TK * VSTR) * 2;

        // ---- S = Q @ K^T - MFIX (offset in pad col) ----
        float sacc[8][4];
#pragma unroll
        for (int nt = 0; nt < 8; nt++)
#pragma unroll
            for (int j = 0; j < 4; j++) sacc[nt][j] = 0.f;
#pragma unroll
        for (int s = 0; s < 5; s++) {
#pragma unroll
            for (int np = 0; np < 4; np++) {
                uint32_t kf[4];
                ldm4(kf, kbase + ((np * 16 + mrow) * QSTR + s * 16 + mkof) * 2);
                uint32_t b0[2] = { kf[0], kf[2] }, b1[2] = { kf[1], kf[3] };
                mma16(sacc[2 * np],     qf[s], b0);
                mma16(sacc[2 * np + 1], qf[s], b1);
            }
        }

        // ---- P = 2^sacc packed fp16x2; O += P @ V ----
#pragma unroll
        for (int j = 0; j < 4; j++) {
            uint32_t a[4] = {
                ex2h2(sacc[2 * j][0],     sacc[2 * j][1]),
                ex2h2(sacc[2 * j][2],     sacc[2 * j][3]),
                ex2h2(sacc[2 * j + 1][0], sacc[2 * j + 1][1]),
                ex2h2(sacc[2 * j + 1][2], sacc[2 * j + 1][3]) };
            const uint32_t vrow = vbase + ((j * 16 + mrow) * VSTR) * 2;
#pragma unroll
            for (int np = 0; np < 5; np++) {   // np=4 covers cols 64..79 (incl. ones col)
                uint32_t vf[4];
                ldm4t(vf, vrow + np * 32 + (mi >> 1) * 16);
                uint32_t b0[2] = { vf[0], vf[1] }, b1[2] = { vf[2], vf[3] };
                mma16(oacc[2 * np],     a, b0);
                mma16(oacc[2 * np + 1], a, b1);
            }
        }
    }

    // ---- epilogue: l from ones column (oacc[9]) ----
    const float l_lo = __shfl_sync(0xffffffffu, oacc[9][0], lane & 28);
    const float l_hi = __shfl_sync(0xffffffffu, oacc[9][2], lane & 28);
    const float inv_lo = 1.f / l_lo, inv_hi = 1.f / l_hi;
    const int b = bh >> 4, h = bh & 15;
    const int n_lo = m0 + wid * 16 + g;
    __half* po_lo = ao + ((size_t)(b * SEQ) + n_lo) * DIM + h * HDIM;
    __half* po_hi = po_lo + (size_t)8 * DIM;
#pragma unroll
    for (int nt = 0; nt < 9; nt++) {
        const int col = nt * 8 + 2 * t;
        *(__half2*)(po_lo + col) = __floats2half2_rn(oacc[nt][0] * inv_lo, oacc[nt][1] * inv_lo);
        *(__half2*)(po_hi + col) = __floats2half2_rn(oacc[nt][2] * inv_hi, oacc[nt][3] * inv_hi);
    }
}

// ---------------- host launcher ----------------
extern "C" void kernel_launch(void* const* d_in, const int* in_sizes, int n_in,
                              void* d_out, int out_size)
{
    const float* x      = (const float*)d_in[0];
    const float* w_qkv  = (const float*)d_in[1];
    const float* b_qkv  = (const float*)d_in[2];
    const float* q_g    = (const float*)d_in[3];
    const float* q_b    = (const float*)d_in[4];
    const float* k_g    = (const float*)d_in[5];
    const float* k_b    = (const float*)d_in[6];
    const float* w_proj = (const float*)d_in[7];
    const float* b_proj = (const float*)d_in[8];
    float* out = (float*)d_out;

    void *p_qkv16, *p_x16, *p_wqkv16, *p_wproj16, *p_qt, *p_kt, *p_vt, *p_ao;
    cudaGetSymbolAddress(&p_qkv16,   g_qkv16);
    cudaGetSymbolAddress(&p_x16,     g_x16);
    cudaGetSymbolAddress(&p_wqkv16,  g_wqkv16);
    cudaGetSymbolAddress(&p_wproj16, g_wproj16);
    cudaGetSymbolAddress(&p_qt,      g_qt);
    cudaGetSymbolAddress(&p_kt,      g_kt);
    cudaGetSymbolAddress(&p_vt,      g_vt);
    cudaGetSymbolAddress(&p_ao,      g_ao);

    const int smemG = 4 * 256 * 40 * 2;   // 81920 B per CTA (4-stage, chunk 32)
    cudaFuncSetAttribute(hgemm<true>,  cudaFuncAttributeMaxDynamicSharedMemorySize, smemG);
    cudaFuncSetAttribute(hgemm<false>, cudaFuncAttributeMaxDynamicSharedMemorySize, smemG);
    cudaFuncSetAttribute(flash_attn, cudaFuncAttributeMaxDynamicSharedMemorySize, SM_FLASH);

    // 0) fp32 -> fp16 conversion
    const int n0 = MROWS * DIM / 4, n1 = O3 * DIM / 4, n2 = DIM * DIM / 4;
    f2h3<<<(n0 + n1 + n2 + 255) / 256, 256>>>(
        x, (__half*)p_x16, n0,
        w_qkv, (__half*)p_wqkv16, n1,
        w_proj, (__half*)p_wproj16, n2);

    // 1) QKV GEMM -> fp16
    hgemm<true><<<dim3(O3 / 128, MROWS / 128), 128, smemG>>>(
        (const __half*)p_x16, (const __half*)p_wqkv16, b_qkv, p_qkv16,
        DIM, DIM, DIM, O3);

    // 2) LayerNorm + transpose -> fp16 (offset carriers in pad col)
    ln_split<<<(BATCH * SEQ * NHEAD) / 8, 256>>>(
        (const __half*)p_qkv16, q_g, q_b, k_g, k_b,
        (__half*)p_qt, (__half*)p_kt, (__half*)p_vt);

    // 3) fused attention
    flash_attn<<<dim3(SEQ / 128, BH), 256, SM_FLASH>>>(
        (const __half*)p_qt, (const __half*)p_kt, (const __half*)p_vt, (__half*)p_ao);

    // 4) projection -> fp32 out
    hgemm<false><<<dim3(DIM / 128, MROWS / 128), 128, smemG>>>(
        (const __half*)p_ao, (const __half*)p_wproj16, b_proj, out,
        DIM, DIM, DIM, DIM);
}